// round 1
// baseline (speedup 1.0000x reference)
#include <cuda_runtime.h>

#define BATCH   32
#define DMODEL  256
#define WIN     25
#define NPOS    625
#define NHEAD   8
#define DHEAD   32
#define QKVCOLS 768

// ---------------- scratch (device globals; no allocation allowed) ----------------
__device__ __align__(16) float g_Q[(size_t)BATCH*NHEAD*NPOS*DHEAD];
__device__ __align__(16) float g_K[(size_t)BATCH*NHEAD*NPOS*DHEAD];
__device__ __align__(16) float g_V[(size_t)BATCH*NHEAD*NPOS*DHEAD];
__device__ __align__(16) float g_O[(size_t)BATCH*NPOS*DMODEL];

// ======================= Kernel 1: QKV projection =======================
// C[m, c] = sum_k x[b, k, m] * Wqkv[k, c];  m = spatial pos (n), c in [0,768)
// Split c into (part q/k/v, head, dh); q scaled by 1/sqrt(32).
__global__ __launch_bounds__(256) void qkv_kernel(const float* __restrict__ x,
                                                  const float* __restrict__ Wqkv)
{
    __shared__ float As[16][64];
    __shared__ float Bs[16][64];
    const int b  = blockIdx.z;
    const int m0 = blockIdx.x * 64;
    const int c0 = blockIdx.y * 64;
    const int t  = threadIdx.x;
    const int tx = t & 15, ty = t >> 4;

    float acc[4][4];
#pragma unroll
    for (int i = 0; i < 4; i++)
#pragma unroll
        for (int j = 0; j < 4; j++) acc[i][j] = 0.f;

    const float* xb = x + (size_t)b * DMODEL * NPOS;
    const int lm = t & 63;      // 0..63
    const int lk = t >> 6;      // 0..3

    for (int k0 = 0; k0 < DMODEL; k0 += 16) {
#pragma unroll
        for (int i = 0; i < 4; i++) {
            int k = lk * 4 + i;
            int m = m0 + lm;
            As[k][lm] = (m < NPOS) ? xb[(size_t)(k0 + k) * NPOS + m] : 0.f;
            Bs[k][lm] = Wqkv[(size_t)(k0 + k) * QKVCOLS + c0 + lm];
        }
        __syncthreads();
#pragma unroll
        for (int kk = 0; kk < 16; kk++) {
            float4 a  = *(const float4*)&As[kk][ty * 4];
            float4 bb = *(const float4*)&Bs[kk][tx * 4];
            float av[4] = {a.x, a.y, a.z, a.w};
            float bv[4] = {bb.x, bb.y, bb.z, bb.w};
#pragma unroll
            for (int i = 0; i < 4; i++)
#pragma unroll
                for (int j = 0; j < 4; j++) acc[i][j] += av[i] * bv[j];
        }
        __syncthreads();
    }

    const float scale = 0.17677669529663687f;  // 32^-0.5
#pragma unroll
    for (int i = 0; i < 4; i++) {
        int m = m0 + ty * 4 + i;
        if (m >= NPOS) continue;
#pragma unroll
        for (int j = 0; j < 4; j++) {
            int c    = c0 + tx * 4 + j;
            int part = c >> 8;
            int rem  = c & 255;
            int h    = rem >> 5;
            int dh   = rem & 31;
            float v  = acc[i][j];
            float* dst = (part == 0) ? g_Q : (part == 1 ? g_K : g_V);
            if (part == 0) v *= scale;
            dst[(((size_t)b * NHEAD + h) * NPOS + m) * DHEAD + dh] = v;
        }
    }
}

// ======================= Kernel 2: attention =======================
// One CTA per (b, h). K (transposed), V, bias column resident in smem.
// Flash-style online softmax; each warp processes 4 query rows at a time,
// each lane owns 4 keys (sim phase) then remaps lane<->dim via smem P tile (PV phase).
#define SMEM_FLOATS (20480 + 20480 + 2404 + 4096 + 1024)  // Kt + Vs + bias + P + Q

__global__ __launch_bounds__(256) void attn_kernel(const float* __restrict__ rel_emb)
{
    extern __shared__ float sm[];
    float* Kt = sm;                 // [32][640], cols 625..639 zero
    float* Vs = sm + 20480;         // [640][32], rows 625..639 zero
    float* Bi = Vs + 20480;         // 2401 bias values for this head (+pad)
    float* Ps = Bi + 2404;          // 8 warps * [4][128]
    float* Qs = Ps + 4096;          // 8 warps * [32][4]

    const int bh   = blockIdx.x;
    const int h    = bh & 7;
    const int b    = bh >> 3;
    const int t    = threadIdx.x;
    const int lane = t & 31;
    const int warp = t >> 5;

    // ---- stage K (transposed), V, bias into smem ----
    const float4* Kg = (const float4*)(g_K + (size_t)bh * NPOS * DHEAD);
    const float4* Vg = (const float4*)(g_V + (size_t)bh * NPOS * DHEAD);
    for (int idx = t; idx < 5000; idx += 256) {          // 5000 float4 = 625*32 floats
        float4 kv = Kg[idx];
        int j = idx >> 3;
        int d = (idx & 7) << 2;
        Kt[(d + 0) * 640 + j] = kv.x;
        Kt[(d + 1) * 640 + j] = kv.y;
        Kt[(d + 2) * 640 + j] = kv.z;
        Kt[(d + 3) * 640 + j] = kv.w;
        ((float4*)Vs)[idx] = Vg[idx];
    }
    for (int idx = t; idx < 480; idx += 256) {           // zero pad region
        int d = idx / 15, j = 625 + idx % 15;
        Kt[d * 640 + j] = 0.f;
        Vs[20000 + idx] = 0.f;
    }
    for (int idx = t; idx < 2401; idx += 256) Bi[idx] = rel_emb[idx * NHEAD + h];
    __syncthreads();

    const float* Qg = g_Q + (size_t)bh * NPOS * DHEAD;
    float* Qw = Qs + warp * 128;   // [d][4 rows]
    float* Pw = Ps + warp * 512;   // [4 rows][128 keys]
    float* gO = g_O + (size_t)b * NPOS * DMODEL + h * DHEAD;

    for (int g = warp; g < 157; g += 8) {
        const int r0 = g * 4;
        // load q for 4 rows; lane == dim
        {
            float q0 = (r0 + 0 < NPOS) ? Qg[(size_t)(r0 + 0) * 32 + lane] : 0.f;
            float q1 = (r0 + 1 < NPOS) ? Qg[(size_t)(r0 + 1) * 32 + lane] : 0.f;
            float q2 = (r0 + 2 < NPOS) ? Qg[(size_t)(r0 + 2) * 32 + lane] : 0.f;
            float q3 = (r0 + 3 < NPOS) ? Qg[(size_t)(r0 + 3) * 32 + lane] : 0.f;
            *(float4*)&Qw[lane * 4] = make_float4(q0, q1, q2, q3);
        }
        __syncwarp();

        int ci[4];
#pragma unroll
        for (int r = 0; r < 4; r++) {
            int row = r0 + r; if (row > NPOS - 1) row = NPOS - 1;
            ci[r] = (row / WIN) * 49 + (row % WIN) + 1200;  // + (w-1)*(2w-1)+(w-1)
        }
        float m_run[4], l_run[4], o[4];
#pragma unroll
        for (int r = 0; r < 4; r++) { m_run[r] = -1e30f; l_run[r] = 0.f; o[r] = 0.f; }

        for (int blk = 0; blk < 5; blk++) {
            const int jb = blk * 128;
            const int j0 = jb + lane * 4;
            float accs[4][4];
            // init with relative-position bias (or -inf for padded keys)
#pragma unroll
            for (int q = 0; q < 4; q++) {
                int j = j0 + q;
                if (j < NPOS) {
                    int cj = (j / WIN) * 49 + (j % WIN);
#pragma unroll
                    for (int r = 0; r < 4; r++) accs[r][q] = Bi[ci[r] - cj];
                } else {
#pragma unroll
                    for (int r = 0; r < 4; r++) accs[r][q] = -1e30f;
                }
            }
            // sim: 4 rows x 4 keys per lane, K from transposed smem
#pragma unroll
            for (int d = 0; d < 32; d++) {
                float4 kq = *(const float4*)&Kt[d * 640 + j0];
                float4 qr = *(const float4*)&Qw[d * 4];
                accs[0][0] += qr.x * kq.x; accs[0][1] += qr.x * kq.y; accs[0][2] += qr.x * kq.z; accs[0][3] += qr.x * kq.w;
                accs[1][0] += qr.y * kq.x; accs[1][1] += qr.y * kq.y; accs[1][2] += qr.y * kq.z; accs[1][3] += qr.y * kq.w;
                accs[2][0] += qr.z * kq.x; accs[2][1] += qr.z * kq.y; accs[2][2] += qr.z * kq.z; accs[2][3] += qr.z * kq.w;
                accs[3][0] += qr.w * kq.x; accs[3][1] += qr.w * kq.y; accs[3][2] += qr.w * kq.z; accs[3][3] += qr.w * kq.w;
            }
            // online softmax per row
#pragma unroll
            for (int r = 0; r < 4; r++) {
                float mx = fmaxf(fmaxf(accs[r][0], accs[r][1]), fmaxf(accs[r][2], accs[r][3]));
#pragma unroll
                for (int off = 16; off > 0; off >>= 1)
                    mx = fmaxf(mx, __shfl_xor_sync(0xffffffffu, mx, off));
                float newm = fmaxf(m_run[r], mx);
                float corr = __expf(m_run[r] - newm);
                float p0 = __expf(accs[r][0] - newm);
                float p1 = __expf(accs[r][1] - newm);
                float p2 = __expf(accs[r][2] - newm);
                float p3 = __expf(accs[r][3] - newm);
                float s  = (p0 + p1) + (p2 + p3);
#pragma unroll
                for (int off = 16; off > 0; off >>= 1)
                    s += __shfl_xor_sync(0xffffffffu, s, off);
                l_run[r] = l_run[r] * corr + s;
                o[r]    *= corr;
                m_run[r] = newm;
                *(float4*)&Pw[r * 128 + lane * 4] = make_float4(p0, p1, p2, p3);
            }
            __syncwarp();
            // PV: lane == dim, broadcast P rows
#pragma unroll
            for (int j4 = 0; j4 < 128; j4 += 4) {
                float4 pr0 = *(const float4*)&Pw[0 * 128 + j4];
                float4 pr1 = *(const float4*)&Pw[1 * 128 + j4];
                float4 pr2 = *(const float4*)&Pw[2 * 128 + j4];
                float4 pr3 = *(const float4*)&Pw[3 * 128 + j4];
                int jj = (jb + j4) * 32 + lane;
                float v0 = Vs[jj];
                float v1 = Vs[jj + 32];
                float v2 = Vs[jj + 64];
                float v3 = Vs[jj + 96];
                o[0] += pr0.x * v0 + pr0.y * v1 + pr0.z * v2 + pr0.w * v3;
                o[1] += pr1.x * v0 + pr1.y * v1 + pr1.z * v2 + pr1.w * v3;
                o[2] += pr2.x * v0 + pr2.y * v1 + pr2.z * v2 + pr2.w * v3;
                o[3] += pr3.x * v0 + pr3.y * v1 + pr3.z * v2 + pr3.w * v3;
            }
            __syncwarp();
        }
        // epilogue: normalize and write (b, n, h*32+lane)
#pragma unroll
        for (int r = 0; r < 4; r++) {
            int row = r0 + r;
            if (row < NPOS) gO[(size_t)row * DMODEL + lane] = o[r] / l_run[r];
        }
        __syncwarp();
    }
}

// ======================= Kernel 3: output projection =======================
// y[b, c, m] = sum_k g_O[b, m, k] * Wout[k, c]
__global__ __launch_bounds__(256) void proj_kernel(const float* __restrict__ Wout,
                                                   float* __restrict__ y)
{
    __shared__ float As[16][68];   // pad 68 to avoid 16-way store conflicts
    __shared__ float Bs[16][64];
    const int b  = blockIdx.z;
    const int m0 = blockIdx.x * 64;
    const int c0 = blockIdx.y * 64;
    const int t  = threadIdx.x;
    const int tx = t & 15, ty = t >> 4;

    float acc[4][4];
#pragma unroll
    for (int i = 0; i < 4; i++)
#pragma unroll
        for (int j = 0; j < 4; j++) acc[i][j] = 0.f;

    const float* A = g_O + (size_t)b * NPOS * DMODEL;
    const int ka = t & 15, ma = t >> 4;   // A loader
    const int lc = t & 63, lk = t >> 6;   // B loader

    for (int k0 = 0; k0 < DMODEL; k0 += 16) {
#pragma unroll
        for (int i = 0; i < 4; i++) {
            int m  = ma + i * 16;
            int gm = m0 + m;
            As[ka][m] = (gm < NPOS) ? A[(size_t)gm * DMODEL + k0 + ka] : 0.f;
        }
#pragma unroll
        for (int i = 0; i < 4; i++)
            Bs[lk * 4 + i][lc] = Wout[(size_t)(k0 + lk * 4 + i) * DMODEL + c0 + lc];
        __syncthreads();
#pragma unroll
        for (int kk = 0; kk < 16; kk++) {
            float4 a  = *(const float4*)&As[kk][ty * 4];
            float4 bb = *(const float4*)&Bs[kk][tx * 4];
            float av[4] = {a.x, a.y, a.z, a.w};
            float bv[4] = {bb.x, bb.y, bb.z, bb.w};
#pragma unroll
            for (int i = 0; i < 4; i++)
#pragma unroll
                for (int j = 0; j < 4; j++) acc[i][j] += av[i] * bv[j];
        }
        __syncthreads();
    }

#pragma unroll
    for (int i = 0; i < 4; i++) {
        int m = m0 + ty * 4 + i;
        if (m >= NPOS) continue;
#pragma unroll
        for (int j = 0; j < 4; j++) {
            int c = c0 + tx * 4 + j;
            y[((size_t)b * DMODEL + c) * NPOS + m] = acc[i][j];
        }
    }
}

// ======================= launch =======================
extern "C" void kernel_launch(void* const* d_in, const int* in_sizes, int n_in,
                              void* d_out, int out_size)
{
    (void)in_sizes; (void)n_in; (void)out_size;
    const float* x    = (const float*)d_in[0];
    const float* Wqkv = (const float*)d_in[1];
    const float* Wout = (const float*)d_in[2];
    const float* rel  = (const float*)d_in[3];
    float* out = (float*)d_out;

    qkv_kernel<<<dim3(10, 12, BATCH), 256>>>(x, Wqkv);

    cudaFuncSetAttribute(attn_kernel, cudaFuncAttributeMaxDynamicSharedMemorySize,
                         SMEM_FLOATS * (int)sizeof(float));
    attn_kernel<<<BATCH * NHEAD, 256, SMEM_FLOATS * (int)sizeof(float)>>>(rel);

    proj_kernel<<<dim3(10, 4, BATCH), 256>>>(Wout, out);
}